// round 12
// baseline (speedup 1.0000x reference)
#include <cuda_runtime.h>
#include <cuda_fp16.h>
#include <math.h>
#include <stdint.h>

#define NLEV 12
#define PRIME1 2654435761u
#define PRIME2 805459861u
#define HMASK ((1u << 21) - 1u)

struct LevelSpec {
    float    scale[NLEV];
    unsigned off[NLEV];
    unsigned res1[NLEV];
    unsigned hashed[NLEV];
};

__device__ float g_S[8192];
__device__ float g_part[256];

// fp16 copy of table_op: one u32 = half2 (feature pair) per entry.
__device__ __align__(8) unsigned g_tb_h[17700000];

// fp16 opacity layer-1 weights (scratch, filled by convert_kernel)
__device__ __half2 g_w1h[768];
__device__ __half2 g_b1h[32];

typedef unsigned long long u64;

// Constant-memory weights.
__constant__ __half2 c_b1h[32];    // opacity bias pairs (units 2j,2j+1)
__constant__ float   c_w2o[64];
__constant__ float   c_b2o[1];
__constant__ u64     c_w1c[768];   // confidence path fp32 f32x2
__constant__ u64     c_b1c[32];
__constant__ float   c_w2c[64];
__constant__ float   c_b2c[1];

// ---------- packed f32x2 helpers (conf path) ----------
__device__ __forceinline__ u64 bcast_f32x2(float v) {
    u64 d;
    asm("mov.b64 %0, {%1, %1};" : "=l"(d) : "f"(v));
    return d;
}
__device__ __forceinline__ void fma_f32x2(u64& acc, u64 a, u64 b) {
    asm("fma.rn.f32x2 %0, %1, %2, %0;" : "+l"(acc) : "l"(a), "l"(b));
}
__device__ __forceinline__ float2 unpack_f32x2(u64 v) {
    float2 r;
    asm("mov.b64 {%0, %1}, %2;" : "=f"(r.x), "=f"(r.y) : "l"(v));
    return r;
}

// Confidence MLP: fp32 f32x2, constant weights, fully unrolled.
__device__ __forceinline__ float tiny_mlp_c(const float* feat) {
    u64 acc[32];
#pragma unroll
    for (int j = 0; j < 32; j++) acc[j] = c_b1c[j];
#pragma unroll
    for (int k = 0; k < 24; k++) {
        u64 bf = bcast_f32x2(feat[k]);
#pragma unroll
        for (int j = 0; j < 32; j++) fma_f32x2(acc[j], bf, c_w1c[k * 32 + j]);
    }
    float out = c_b2c[0];
#pragma unroll
    for (int j = 0; j < 32; j++) {
        float2 h = unpack_f32x2(acc[j]);
        out += fmaxf(h.x, 0.0f) * c_w2c[2 * j];
        out += fmaxf(h.y, 0.0f) * c_w2c[2 * j + 1];
    }
    return out;
}

// ---------- merged conversion (table + weights) ----------
__global__ void convert_kernel(const float4* __restrict__ src, unsigned n4,
                               const float* __restrict__ w1, const float* __restrict__ b1) {
    unsigned i = blockIdx.x * blockDim.x + threadIdx.x;
    if (i < n4) {
        float4 v = __ldg(src + i);
        __half2 a = __floats2half2_rn(v.x, v.y);
        __half2 b = __floats2half2_rn(v.z, v.w);
        g_tb_h[2 * i]     = *(unsigned*)&a;
        g_tb_h[2 * i + 1] = *(unsigned*)&b;
    }
    if (i < 768) g_w1h[i] = __floats2half2_rn(w1[2 * i], w1[2 * i + 1]);
    if (i < 32)  g_b1h[i] = __floats2half2_rn(b1[2 * i], b1[2 * i + 1]);
}

__device__ __forceinline__ __half2 tb_fetch_h(unsigned idx) {
    unsigned raw = __ldg(&g_tb_h[idx]);
    return *(__half2*)&raw;
}
__device__ __forceinline__ unsigned h2_u32(__half2 h) { return *(unsigned*)&h; }

// W1 element (k<24) else 0. n in [0,64).
__device__ __forceinline__ __half w1_elem(int k, int n) {
    if (k >= 24) return __ushort_as_half((unsigned short)0);
    __half2 hv = g_w1h[k * 32 + (n >> 1)];
    return (n & 1) ? __high2half(hv) : __low2half(hv);
}

// ========================== opacity path: B*P 3-D points ==========================
#define A_STRIDE 80   // bytes per staged A row (16B aligned)

__global__ void __launch_bounds__(128, 6)
opacity_kernel(const float* __restrict__ pts, const float* __restrict__ gt,
               LevelSpec sp, int P) {
    __shared__ __align__(16) float s_pts[3072];
    __shared__ float s_red[128];
    __shared__ unsigned s_bf0[512];                 // B frag reg0 per tile t, lane
    __shared__ unsigned s_bf1[512];                 // B frag reg1
    __shared__ __align__(16) char s_A[4 * 32 * A_STRIDE];  // per-warp A staging

    const int tid  = threadIdx.x;
    const int wid  = tid >> 5;
    const int lane = tid & 31;
    const int b = blockIdx.x;
    const float* ptb = pts + (size_t)b * P * 3;
    const float* gtb = gt + (size_t)b * P;

    // stage points
    {
        int n4 = (3 * P) / 4;
        const float4* src4 = (const float4*)ptb;
        for (int i = tid; i < n4; i += 128) ((float4*)s_pts)[i] = src4[i];
        for (int i = 4 * n4 + tid; i < 3 * P; i += 128) s_pts[i] = ptb[i];
    }
    // build B fragments (warp 0): tile t = kt*8 + nt
    if (tid < 32) {
        for (int t = 0; t < 16; t++) {
            int kt = t >> 3, nt = t & 7;
            int n  = nt * 8 + (tid >> 2);
            int k0 = kt * 16 + (tid & 3) * 2;
            __half2 r0 = __halves2half2(w1_elem(k0, n),     w1_elem(k0 + 1, n));
            __half2 r1 = __halves2half2(w1_elem(k0 + 8, n), w1_elem(k0 + 9, n));
            s_bf0[t * 32 + tid] = h2_u32(r0);
            s_bf1[t * 32 + tid] = h2_u32(r1);
        }
    }
    __syncthreads();

    const float b2 = c_b2o[0];
    char* warpA = s_A + wid * 32 * A_STRIDE;
    float lsum = 0.0f;
    const int ITER = (P + 127) >> 7;

    for (int it = 0; it < ITER; it++) {
        const int pb = it * 128 + wid * 32;
        const int p  = pb + lane;
        const bool valid = p < P;

        __half2 feat2[12];
        if (valid) {
            float u0 = (s_pts[3 * p + 0] + 1.0f) * 0.5f;
            float u1 = (s_pts[3 * p + 1] + 1.0f) * 0.5f;
            float u2 = (s_pts[3 * p + 2] + 1.0f) * 0.5f;
#pragma unroll
            for (int l = 0; l < NLEV; l++) {
                const float s = sp.scale[l];
                float px = u0 * s + 0.5f, py = u1 * s + 0.5f, pz = u2 * s + 0.5f;
                float fx = floorf(px), fy = floorf(py), fz = floorf(pz);
                float ax = px - fx, ay = py - fy, az = pz - fz;
                unsigned ix = (unsigned)fx, iy = (unsigned)fy, iz = (unsigned)fz;

                unsigned id[8];
                if (sp.hashed[l]) {
                    unsigned hy0 = iy * PRIME1, hy1 = hy0 + PRIME1;
                    unsigned hz0 = iz * PRIME2, hz1 = hz0 + PRIME2;
                    unsigned a0 = ix ^ hy0, a1 = (ix + 1u) ^ hy0;
                    unsigned a2 = ix ^ hy1, a3 = (ix + 1u) ^ hy1;
                    id[0] = (a0 ^ hz0) & HMASK; id[1] = (a1 ^ hz0) & HMASK;
                    id[2] = (a2 ^ hz0) & HMASK; id[3] = (a3 ^ hz0) & HMASK;
                    id[4] = (a0 ^ hz1) & HMASK; id[5] = (a1 ^ hz1) & HMASK;
                    id[6] = (a2 ^ hz1) & HMASK; id[7] = (a3 ^ hz1) & HMASK;
                } else {
                    unsigned s1 = sp.res1[l], s2 = s1 * s1;
                    unsigned base = ix + iy * s1 + iz * s2;
                    id[0] = base;           id[1] = base + 1u;
                    id[2] = base + s1;      id[3] = base + s1 + 1u;
                    id[4] = base + s2;      id[5] = base + s2 + 1u;
                    id[6] = base + s2 + s1; id[7] = base + s2 + s1 + 1u;
                }
                const unsigned off = sp.off[l];
                __half2 v0 = tb_fetch_h(off + id[0]);
                __half2 v1 = tb_fetch_h(off + id[1]);
                __half2 v2 = tb_fetch_h(off + id[2]);
                __half2 v3 = tb_fetch_h(off + id[3]);
                __half2 v4 = tb_fetch_h(off + id[4]);
                __half2 v5 = tb_fetch_h(off + id[5]);
                __half2 v6 = tb_fetch_h(off + id[6]);
                __half2 v7 = tb_fetch_h(off + id[7]);

                float wx0 = 1.0f - ax, wy0 = 1.0f - ay, wz0 = 1.0f - az;
                float w00 = wx0 * wy0, w10 = ax * wy0, w01 = wx0 * ay, w11 = ax * ay;

                __half2 f = __hmul2(__float2half2_rn(w00 * wz0), v0);
                f = __hfma2(__float2half2_rn(w10 * wz0), v1, f);
                f = __hfma2(__float2half2_rn(w01 * wz0), v2, f);
                f = __hfma2(__float2half2_rn(w11 * wz0), v3, f);
                f = __hfma2(__float2half2_rn(w00 * az),  v4, f);
                f = __hfma2(__float2half2_rn(w10 * az),  v5, f);
                f = __hfma2(__float2half2_rn(w01 * az),  v6, f);
                f = __hfma2(__float2half2_rn(w11 * az),  v7, f);
                feat2[l] = f;
            }
        } else {
            __half2 z = __float2half2_rn(0.0f);
#pragma unroll
            for (int l = 0; l < NLEV; l++) feat2[l] = z;
        }

        // stage A row (32 halves: 24 feats + 8 zero pad)
        __syncwarp();
        {
            char* row = warpA + lane * A_STRIDE;
#pragma unroll
            for (int j = 0; j < 6; j++) {
                u64 w = (u64)h2_u32(feat2[2 * j]) | ((u64)h2_u32(feat2[2 * j + 1]) << 32);
                *(u64*)(row + j * 8) = w;
            }
            *(u64*)(row + 48) = 0ull;
            *(u64*)(row + 56) = 0ull;
        }
        __syncwarp();

        // warp MMA: [32x32] x [32x64]
        float rs[4] = {0.f, 0.f, 0.f, 0.f};   // [mt*2 + rr]
        const int jcol = (lane & 3);
        const int rloc = (lane & 7) | (((lane >> 3) & 1) << 3);
        const int chalf = lane >> 4;
#pragma unroll
        for (int mt = 0; mt < 2; mt++) {
            unsigned a0[4], a1[4];
            {
                unsigned sa0 = (unsigned)__cvta_generic_to_shared(
                    warpA + (mt * 16 + rloc) * A_STRIDE + 0 * 32 + chalf * 16);
                asm volatile("ldmatrix.sync.aligned.m8n8.x4.shared.b16 {%0,%1,%2,%3}, [%4];"
                             : "=r"(a0[0]), "=r"(a0[1]), "=r"(a0[2]), "=r"(a0[3]) : "r"(sa0));
                unsigned sa1 = (unsigned)__cvta_generic_to_shared(
                    warpA + (mt * 16 + rloc) * A_STRIDE + 1 * 32 + chalf * 16);
                asm volatile("ldmatrix.sync.aligned.m8n8.x4.shared.b16 {%0,%1,%2,%3}, [%4];"
                             : "=r"(a1[0]), "=r"(a1[1]), "=r"(a1[2]), "=r"(a1[3]) : "r"(sa1));
            }
#pragma unroll
            for (int nt = 0; nt < 8; nt++) {
                int j = nt * 4 + jcol;                      // bias/w2 pair index (cols 2j,2j+1)
                unsigned bias = ((const unsigned*)c_b1h)[j];
                unsigned c0 = bias, c1 = bias;
                unsigned b00 = s_bf0[nt * 32 + lane], b01 = s_bf1[nt * 32 + lane];
                asm volatile("mma.sync.aligned.m16n8k16.row.col.f16.f16.f16.f16 "
                             "{%0,%1}, {%2,%3,%4,%5}, {%6,%7}, {%0,%1};"
                             : "+r"(c0), "+r"(c1)
                             : "r"(a0[0]), "r"(a0[1]), "r"(a0[2]), "r"(a0[3]), "r"(b00), "r"(b01));
                unsigned b10 = s_bf0[(8 + nt) * 32 + lane], b11 = s_bf1[(8 + nt) * 32 + lane];
                asm volatile("mma.sync.aligned.m16n8k16.row.col.f16.f16.f16.f16 "
                             "{%0,%1}, {%2,%3,%4,%5}, {%6,%7}, {%0,%1};"
                             : "+r"(c0), "+r"(c1)
                             : "r"(a1[0]), "r"(a1[1]), "r"(a1[2]), "r"(a1[3]), "r"(b10), "r"(b11));

                __half2 z = __float2half2_rn(0.0f);
                __half2 h0 = __hmax2(*(__half2*)&c0, z);
                __half2 h1 = __hmax2(*(__half2*)&c1, z);
                float2 f0 = __half22float2(h0);
                float2 f1 = __half22float2(h1);
                float2 w2p = ((const float2*)c_w2o)[j];
                rs[mt * 2 + 0] += f0.x * w2p.x + f0.y * w2p.y;
                rs[mt * 2 + 1] += f1.x * w2p.x + f1.y * w2p.y;
            }
        }
        // reduce over the 4 lanes of each row group
#pragma unroll
        for (int i = 0; i < 4; i++) {
            rs[i] += __shfl_xor_sync(0xffffffffu, rs[i], 1);
            rs[i] += __shfl_xor_sync(0xffffffffu, rs[i], 2);
        }
        if ((lane & 3) == 0) {
            int rbase = lane >> 2;
#pragma unroll
            for (int mt = 0; mt < 2; mt++) {
#pragma unroll
                for (int rr = 0; rr < 2; rr++) {
                    int r = mt * 16 + rbase + rr * 8;
                    int p2 = pb + r;
                    if (p2 < P) {
                        float op = rs[mt * 2 + rr] + b2;
                        float lw = (p2 < 500) ? (4.0f / 3.0f) : (2.0f / 3.0f);
                        lsum += fabsf(op - __ldg(gtb + p2)) * lw;
                    }
                }
            }
        }
    }

    s_red[tid] = lsum;
    __syncthreads();
#pragma unroll
    for (int st = 64; st > 0; st >>= 1) {
        if (tid < st) s_red[tid] += s_red[tid + st];
        __syncthreads();
    }
    if (tid == 0) g_S[b] = s_red[0] * (1.0f / (float)P);
}

// ========================== confidence path ==========================
__global__ void __launch_bounds__(128, 4)
conf_kernel(const float* __restrict__ line, const float* __restrict__ table,
            LevelSpec sp, int B) {
    __shared__ float s_red[128];
    const int tid = threadIdx.x;

    const int i = blockIdx.x * 128 + tid;
    float val = 0.0f;
    if (i < B) {
        const float2* tb = (const float2*)table;
        float u0 = (__ldg(line + 2 * i) + 1.0f) * 0.5f;
        float u1 = (__ldg(line + 2 * i + 1) + 1.0f) * 0.5f;

        float feat[24];
#pragma unroll
        for (int l = 0; l < NLEV; l++) {
            const float s = sp.scale[l];
            float px = u0 * s + 0.5f, py = u1 * s + 0.5f;
            float fx = floorf(px), fy = floorf(py);
            float ax = px - fx, ay = py - fy;
            unsigned ix = (unsigned)fx, iy = (unsigned)fy;

            unsigned id[4];
            if (sp.hashed[l]) {
                unsigned hy0 = iy * PRIME1, hy1 = hy0 + PRIME1;
                id[0] = (ix ^ hy0) & HMASK; id[1] = ((ix + 1u) ^ hy0) & HMASK;
                id[2] = (ix ^ hy1) & HMASK; id[3] = ((ix + 1u) ^ hy1) & HMASK;
            } else {
                unsigned s1 = sp.res1[l];
                unsigned base = ix + iy * s1;
                id[0] = base;      id[1] = base + 1u;
                id[2] = base + s1; id[3] = base + s1 + 1u;
            }
            const unsigned off = sp.off[l];
            float2 v0 = __ldg(tb + off + id[0]);
            float2 v1 = __ldg(tb + off + id[1]);
            float2 v2 = __ldg(tb + off + id[2]);
            float2 v3 = __ldg(tb + off + id[3]);

            float wx0 = 1.0f - ax, wy0 = 1.0f - ay;
            float c0 = wx0 * wy0, c1 = ax * wy0, c2 = wx0 * ay, c3 = ax * ay;
            float fxo = c0 * v0.x; fxo += c1 * v1.x; fxo += c2 * v2.x; fxo += c3 * v3.x;
            float fyo = c0 * v0.y; fyo += c1 * v1.y; fyo += c2 * v2.y; fyo += c3 * v3.y;
            feat[2 * l] = fxo;
            feat[2 * l + 1] = fyo;
        }
        float conf = tiny_mlp_c(feat);
        val = expf(-conf) * g_S[i] + conf;
    }

    s_red[tid] = val;
    __syncthreads();
#pragma unroll
    for (int st = 64; st > 0; st >>= 1) {
        if (tid < st) s_red[tid] += s_red[tid + st];
        __syncthreads();
    }
    if (tid == 0) g_part[blockIdx.x] = s_red[0];
}

__global__ void final_kernel(float* out, int nb, float invB) {
    __shared__ float sr[256];
    int t = threadIdx.x;
    sr[t] = (t < nb) ? g_part[t] : 0.0f;
    __syncthreads();
#pragma unroll
    for (int st = 128; st > 0; st >>= 1) {
        if (t < st) sr[t] += sr[t + st];
        __syncthreads();
    }
    if (t == 0) out[0] = sr[0] * invB;
}

// ---------- host: replicate _level_specs exactly ----------
static void make_specs(int D, LevelSpec* sp) {
    double f = pow(8192.0 / 16.0, 1.0 / 11.0);
    long long offset = 0;
    for (int l = 0; l < NLEV; l++) {
        double scale = 16.0 * pow(f, (double)l) - 1.0;
        long long res = (long long)ceil(scale) + 1;
        long long dense = 1;
        for (int d = 0; d < D; d++) dense *= (res + 1);
        long long params = dense;
        if (params > (1LL << 21)) params = (1LL << 21);
        params = ((params + 7) / 8) * 8;
        sp->scale[l]  = (float)scale;
        sp->off[l]    = (unsigned)offset;
        sp->res1[l]   = (unsigned)(res + 1);
        sp->hashed[l] = (dense > (1LL << 21)) ? 1u : 0u;
        offset += params;
    }
}

extern "C" void kernel_launch(void* const* d_in, const int* in_sizes, int n_in,
                              void* d_out, int out_size) {
    const float* line  = (const float*)d_in[0];
    const float* pts   = (const float*)d_in[1];
    const float* gt    = (const float*)d_in[2];
    const float* tconf = (const float*)d_in[3];
    const float* w1c   = (const float*)d_in[4];
    const float* b1c   = (const float*)d_in[5];
    const float* w2c   = (const float*)d_in[6];
    const float* b2c   = (const float*)d_in[7];
    const float* top   = (const float*)d_in[8];
    const float* w1o   = (const float*)d_in[9];
    const float* b1o   = (const float*)d_in[10];
    const float* w2o   = (const float*)d_in[11];
    const float* b2o   = (const float*)d_in[12];

    int B = in_sizes[0] / 2;
    int P = in_sizes[1] / (3 * B);
    unsigned tot3 = (unsigned)(in_sizes[8] / 2);

    LevelSpec sp3, sp2;
    make_specs(3, &sp3);
    make_specs(2, &sp2);

    cudaMemcpyToSymbolAsync(c_w1c, w1c, 1536 * sizeof(float), 0, cudaMemcpyDeviceToDevice);
    cudaMemcpyToSymbolAsync(c_b1c, b1c, 64 * sizeof(float),   0, cudaMemcpyDeviceToDevice);
    cudaMemcpyToSymbolAsync(c_w2c, w2c, 64 * sizeof(float),   0, cudaMemcpyDeviceToDevice);
    cudaMemcpyToSymbolAsync(c_b2c, b2c, sizeof(float),        0, cudaMemcpyDeviceToDevice);
    cudaMemcpyToSymbolAsync(c_w2o, w2o, 64 * sizeof(float),   0, cudaMemcpyDeviceToDevice);
    cudaMemcpyToSymbolAsync(c_b2o, b2o, sizeof(float),        0, cudaMemcpyDeviceToDevice);

    unsigned n4 = tot3 / 2;
    convert_kernel<<<(n4 + 255) / 256, 256>>>((const float4*)top, n4, w1o, b1o);

    void* p_b1h = nullptr;
    cudaGetSymbolAddress(&p_b1h, g_b1h);
    cudaMemcpyToSymbolAsync(c_b1h, p_b1h, 32 * sizeof(__half2), 0, cudaMemcpyDeviceToDevice);

    opacity_kernel<<<B, 128>>>(pts, gt, sp3, P);

    int nb = (B + 127) / 128;
    if (nb > 256) nb = 256;
    conf_kernel<<<nb, 128>>>(line, tconf, sp2, B);
    final_kernel<<<1, 256>>>((float*)d_out, nb, 1.0f / (float)B);
}

// round 13
// speedup vs baseline: 1.2535x; 1.2535x over previous
#include <cuda_runtime.h>
#include <cuda_fp16.h>
#include <math.h>
#include <stdint.h>

#define NLEV 12
#define PRIME1 2654435761u
#define PRIME2 805459861u
#define HMASK ((1u << 21) - 1u)

struct LevelSpec {
    float    scale[NLEV];
    unsigned off[NLEV];
    unsigned res1[NLEV];    // res + 1 (dense stride base)
    unsigned hashed[NLEV];  // 0/1
};

__device__ float g_Sp[16384];   // per-(line,half) partial weighted-L1 sums
__device__ float g_part[256];   // conf-kernel block partials

// fp16 copy of table_op: one u32 = half2 (feature pair) per entry.
__device__ __align__(8) unsigned g_tb_h[17700000];

// fp16 copies of opacity MLP layer-1 weights (scratch; copied into constant)
__device__ __half2 g_w1h[768];
__device__ __half2 g_b1h[32];

typedef unsigned long long u64;

// MLP weights in constant memory (filled per-launch by async D2D memcpy nodes).
__constant__ __half2 c_w1h[768];   // opacity w1, half2 pairs (units 2j,2j+1)
__constant__ __half2 c_b1h[32];
__constant__ float   c_w2o[64];
__constant__ float   c_b2o[1];
__constant__ u64     c_w1c[768];   // confidence path stays fp32 f32x2
__constant__ u64     c_b1c[32];
__constant__ float   c_w2c[64];
__constant__ float   c_b2c[1];

// ---------- packed f32x2 helpers (conf path) ----------
__device__ __forceinline__ u64 bcast_f32x2(float v) {
    u64 d;
    asm("mov.b64 %0, {%1, %1};" : "=l"(d) : "f"(v));
    return d;
}
__device__ __forceinline__ void fma_f32x2(u64& acc, u64 a, u64 b) {
    asm("fma.rn.f32x2 %0, %1, %2, %0;" : "+l"(acc) : "l"(a), "l"(b));
}
__device__ __forceinline__ float2 unpack_f32x2(u64 v) {
    float2 r;
    asm("mov.b64 {%0, %1}, %2;" : "=f"(r.x), "=f"(r.y) : "l"(v));
    return r;
}

// Opacity MLP: feat arrives as 12 half2 (level pairs). half2 accumulators,
// constant weights, fully unrolled (LDCU path). Identical to R11.
__device__ __forceinline__ float tiny_mlp_h(const __half2* feat2) {
    __half2 acc[32];
#pragma unroll
    for (int j = 0; j < 32; j++) acc[j] = c_b1h[j];
#pragma unroll
    for (int l = 0; l < 12; l++) {
        __half2 f = feat2[l];
        __half2 blo = __low2half2(f);
        __half2 bhi = __high2half2(f);
#pragma unroll
        for (int j = 0; j < 32; j++) acc[j] = __hfma2(blo, c_w1h[(2 * l) * 32 + j], acc[j]);
#pragma unroll
        for (int j = 0; j < 32; j++) acc[j] = __hfma2(bhi, c_w1h[(2 * l + 1) * 32 + j], acc[j]);
    }
    float out = c_b2o[0];
#pragma unroll
    for (int j = 0; j < 32; j++) {
        float2 h = __half22float2(acc[j]);
        out += fmaxf(h.x, 0.0f) * c_w2o[2 * j];
        out += fmaxf(h.y, 0.0f) * c_w2o[2 * j + 1];
    }
    return out;
}

// Confidence MLP: fp32 f32x2 (unchanged).
__device__ __forceinline__ float tiny_mlp_c(const float* feat) {
    u64 acc[32];
#pragma unroll
    for (int j = 0; j < 32; j++) acc[j] = c_b1c[j];
#pragma unroll
    for (int k = 0; k < 24; k++) {
        u64 bf = bcast_f32x2(feat[k]);
#pragma unroll
        for (int j = 0; j < 32; j++) fma_f32x2(acc[j], bf, c_w1c[k * 32 + j]);
    }
    float out = c_b2c[0];
#pragma unroll
    for (int j = 0; j < 32; j++) {
        float2 h = unpack_f32x2(acc[j]);
        out += fmaxf(h.x, 0.0f) * c_w2c[2 * j];
        out += fmaxf(h.y, 0.0f) * c_w2c[2 * j + 1];
    }
    return out;
}

// ---------- merged conversion (table + weights), runs inside the graph ----------
__global__ void convert_kernel(const float4* __restrict__ src, unsigned n4,
                               const float* __restrict__ w1, const float* __restrict__ b1) {
    unsigned i = blockIdx.x * blockDim.x + threadIdx.x;
    if (i < n4) {
        float4 v = __ldg(src + i);
        __half2 a = __floats2half2_rn(v.x, v.y);
        __half2 b = __floats2half2_rn(v.z, v.w);
        g_tb_h[2 * i]     = *(unsigned*)&a;
        g_tb_h[2 * i + 1] = *(unsigned*)&b;
    }
    if (i < 768) g_w1h[i] = __floats2half2_rn(w1[2 * i], w1[2 * i + 1]);
    if (i < 32)  g_b1h[i] = __floats2half2_rn(b1[2 * i], b1[2 * i + 1]);
}

__device__ __forceinline__ __half2 tb_fetch_h(unsigned idx) {
    unsigned raw = __ldg(&g_tb_h[idx]);
    return *(__half2*)&raw;
}

// ========================== opacity path: B*P 3-D points ==========================
// 2 blocks per line: block handles points [h*halfP, end). Hot loop identical to R11.
__global__ void __launch_bounds__(128, 6)
opacity_kernel(const float* __restrict__ pts, const float* __restrict__ gt,
               LevelSpec sp, int P, int halfP) {
    __shared__ __align__(16) float s_pts[1600];
    __shared__ float s_red[128];

    const int tid  = threadIdx.x;
    const int b    = blockIdx.x >> 1;
    const int h    = blockIdx.x & 1;
    const int pstart = h * halfP;
    const int pend   = (h == 0) ? halfP : P;
    const int npts   = pend - pstart;

    const float* ptb = pts + (size_t)b * P * 3 + (size_t)pstart * 3;
    const float* gtb = gt + (size_t)b * P;

    // coalesced stage of this block's point strip into shared
    for (int i = tid; i < npts * 3; i += 128) s_pts[i] = __ldg(ptb + i);
    __syncthreads();

    float lsum = 0.0f;
    for (int q = tid; q < npts; q += 128) {
        const int p = pstart + q;
        float u0 = (s_pts[3 * q + 0] + 1.0f) * 0.5f;
        float u1 = (s_pts[3 * q + 1] + 1.0f) * 0.5f;
        float u2 = (s_pts[3 * q + 2] + 1.0f) * 0.5f;

        __half2 feat2[12];
#pragma unroll
        for (int l = 0; l < NLEV; l++) {
            const float s = sp.scale[l];
            float px = u0 * s + 0.5f, py = u1 * s + 0.5f, pz = u2 * s + 0.5f;
            float fx = floorf(px), fy = floorf(py), fz = floorf(pz);
            float ax = px - fx, ay = py - fy, az = pz - fz;
            unsigned ix = (unsigned)fx, iy = (unsigned)fy, iz = (unsigned)fz;

            unsigned id[8];
            if (sp.hashed[l]) {
                unsigned hy0 = iy * PRIME1, hy1 = hy0 + PRIME1;
                unsigned hz0 = iz * PRIME2, hz1 = hz0 + PRIME2;
                unsigned a0 = ix ^ hy0, a1 = (ix + 1u) ^ hy0;
                unsigned a2 = ix ^ hy1, a3 = (ix + 1u) ^ hy1;
                id[0] = (a0 ^ hz0) & HMASK; id[1] = (a1 ^ hz0) & HMASK;
                id[2] = (a2 ^ hz0) & HMASK; id[3] = (a3 ^ hz0) & HMASK;
                id[4] = (a0 ^ hz1) & HMASK; id[5] = (a1 ^ hz1) & HMASK;
                id[6] = (a2 ^ hz1) & HMASK; id[7] = (a3 ^ hz1) & HMASK;
            } else {
                unsigned s1 = sp.res1[l], s2 = s1 * s1;
                unsigned base = ix + iy * s1 + iz * s2;
                id[0] = base;           id[1] = base + 1u;
                id[2] = base + s1;      id[3] = base + s1 + 1u;
                id[4] = base + s2;      id[5] = base + s2 + 1u;
                id[6] = base + s2 + s1; id[7] = base + s2 + s1 + 1u;
            }
            const unsigned off = sp.off[l];
            __half2 v0 = tb_fetch_h(off + id[0]);
            __half2 v1 = tb_fetch_h(off + id[1]);
            __half2 v2 = tb_fetch_h(off + id[2]);
            __half2 v3 = tb_fetch_h(off + id[3]);
            __half2 v4 = tb_fetch_h(off + id[4]);
            __half2 v5 = tb_fetch_h(off + id[5]);
            __half2 v6 = tb_fetch_h(off + id[6]);
            __half2 v7 = tb_fetch_h(off + id[7]);

            float wx0 = 1.0f - ax, wy0 = 1.0f - ay, wz0 = 1.0f - az;
            float w00 = wx0 * wy0, w10 = ax * wy0, w01 = wx0 * ay, w11 = ax * ay;

            __half2 f = __hmul2(__float2half2_rn(w00 * wz0), v0);
            f = __hfma2(__float2half2_rn(w10 * wz0), v1, f);
            f = __hfma2(__float2half2_rn(w01 * wz0), v2, f);
            f = __hfma2(__float2half2_rn(w11 * wz0), v3, f);
            f = __hfma2(__float2half2_rn(w00 * az),  v4, f);
            f = __hfma2(__float2half2_rn(w10 * az),  v5, f);
            f = __hfma2(__float2half2_rn(w01 * az),  v6, f);
            f = __hfma2(__float2half2_rn(w11 * az),  v7, f);
            feat2[l] = f;
        }

        float op = tiny_mlp_h(feat2);
        float lw = (p < 500) ? (4.0f / 3.0f) : (2.0f / 3.0f);
        lsum += fabsf(op - __ldg(gtb + p)) * lw;
    }

    s_red[tid] = lsum;
    __syncthreads();
#pragma unroll
    for (int st = 64; st > 0; st >>= 1) {
        if (tid < st) s_red[tid] += s_red[tid + st];
        __syncthreads();
    }
    if (tid == 0) g_Sp[blockIdx.x] = s_red[0];
}

// ========================== confidence path: B 2-D lines (fp32 table) ==========================
__global__ void __launch_bounds__(128, 4)
conf_kernel(const float* __restrict__ line, const float* __restrict__ table,
            LevelSpec sp, int B, float invP) {
    __shared__ float s_red[128];
    const int tid = threadIdx.x;

    const int i = blockIdx.x * 128 + tid;
    float val = 0.0f;
    if (i < B) {
        const float2* tb = (const float2*)table;
        float u0 = (__ldg(line + 2 * i) + 1.0f) * 0.5f;
        float u1 = (__ldg(line + 2 * i + 1) + 1.0f) * 0.5f;

        float feat[24];
#pragma unroll
        for (int l = 0; l < NLEV; l++) {
            const float s = sp.scale[l];
            float px = u0 * s + 0.5f, py = u1 * s + 0.5f;
            float fx = floorf(px), fy = floorf(py);
            float ax = px - fx, ay = py - fy;
            unsigned ix = (unsigned)fx, iy = (unsigned)fy;

            unsigned id[4];
            if (sp.hashed[l]) {
                unsigned hy0 = iy * PRIME1, hy1 = hy0 + PRIME1;
                id[0] = (ix ^ hy0) & HMASK; id[1] = ((ix + 1u) ^ hy0) & HMASK;
                id[2] = (ix ^ hy1) & HMASK; id[3] = ((ix + 1u) ^ hy1) & HMASK;
            } else {
                unsigned s1 = sp.res1[l];
                unsigned base = ix + iy * s1;
                id[0] = base;      id[1] = base + 1u;
                id[2] = base + s1; id[3] = base + s1 + 1u;
            }
            const unsigned off = sp.off[l];
            float2 v0 = __ldg(tb + off + id[0]);
            float2 v1 = __ldg(tb + off + id[1]);
            float2 v2 = __ldg(tb + off + id[2]);
            float2 v3 = __ldg(tb + off + id[3]);

            float wx0 = 1.0f - ax, wy0 = 1.0f - ay;
            float c0 = wx0 * wy0, c1 = ax * wy0, c2 = wx0 * ay, c3 = ax * ay;
            float fxo = c0 * v0.x; fxo += c1 * v1.x; fxo += c2 * v2.x; fxo += c3 * v3.x;
            float fyo = c0 * v0.y; fyo += c1 * v1.y; fyo += c2 * v2.y; fyo += c3 * v3.y;
            feat[2 * l] = fxo;
            feat[2 * l + 1] = fyo;
        }
        float conf = tiny_mlp_c(feat);
        float S = (g_Sp[2 * i] + g_Sp[2 * i + 1]) * invP;
        val = expf(-conf) * S + conf;
    }

    s_red[tid] = val;
    __syncthreads();
#pragma unroll
    for (int st = 64; st > 0; st >>= 1) {
        if (tid < st) s_red[tid] += s_red[tid + st];
        __syncthreads();
    }
    if (tid == 0) g_part[blockIdx.x] = s_red[0];
}

__global__ void final_kernel(float* out, int nb, float invB) {
    __shared__ float sr[256];
    int t = threadIdx.x;
    sr[t] = (t < nb) ? g_part[t] : 0.0f;
    __syncthreads();
#pragma unroll
    for (int st = 128; st > 0; st >>= 1) {
        if (t < st) sr[t] += sr[t + st];
        __syncthreads();
    }
    if (t == 0) out[0] = sr[0] * invB;
}

// ---------- host: replicate _level_specs exactly (float64 math) ----------
static void make_specs(int D, LevelSpec* sp) {
    double f = pow(8192.0 / 16.0, 1.0 / 11.0);
    long long offset = 0;
    for (int l = 0; l < NLEV; l++) {
        double scale = 16.0 * pow(f, (double)l) - 1.0;
        long long res = (long long)ceil(scale) + 1;
        long long dense = 1;
        for (int d = 0; d < D; d++) dense *= (res + 1);
        long long params = dense;
        if (params > (1LL << 21)) params = (1LL << 21);
        params = ((params + 7) / 8) * 8;
        sp->scale[l]  = (float)scale;
        sp->off[l]    = (unsigned)offset;
        sp->res1[l]   = (unsigned)(res + 1);
        sp->hashed[l] = (dense > (1LL << 21)) ? 1u : 0u;
        offset += params;
    }
}

extern "C" void kernel_launch(void* const* d_in, const int* in_sizes, int n_in,
                              void* d_out, int out_size) {
    const float* line  = (const float*)d_in[0];
    const float* pts   = (const float*)d_in[1];
    const float* gt    = (const float*)d_in[2];
    const float* tconf = (const float*)d_in[3];
    const float* w1c   = (const float*)d_in[4];
    const float* b1c   = (const float*)d_in[5];
    const float* w2c   = (const float*)d_in[6];
    const float* b2c   = (const float*)d_in[7];
    const float* top   = (const float*)d_in[8];
    const float* w1o   = (const float*)d_in[9];
    const float* b1o   = (const float*)d_in[10];
    const float* w2o   = (const float*)d_in[11];
    const float* b2o   = (const float*)d_in[12];

    int B = in_sizes[0] / 2;
    int P = in_sizes[1] / (3 * B);
    int halfP = (P + 1) / 2;                       // 500 for P=1000
    unsigned tot3 = (unsigned)(in_sizes[8] / 2);   // entries in table_op

    LevelSpec sp3, sp2;
    make_specs(3, &sp3);
    make_specs(2, &sp2);

    // confidence weights (fp32) -> constant
    cudaMemcpyToSymbolAsync(c_w1c, w1c, 1536 * sizeof(float), 0, cudaMemcpyDeviceToDevice);
    cudaMemcpyToSymbolAsync(c_b1c, b1c, 64 * sizeof(float),   0, cudaMemcpyDeviceToDevice);
    cudaMemcpyToSymbolAsync(c_w2c, w2c, 64 * sizeof(float),   0, cudaMemcpyDeviceToDevice);
    cudaMemcpyToSymbolAsync(c_b2c, b2c, sizeof(float),        0, cudaMemcpyDeviceToDevice);
    // opacity fp32 output-layer weights -> constant
    cudaMemcpyToSymbolAsync(c_w2o, w2o, 64 * sizeof(float),   0, cudaMemcpyDeviceToDevice);
    cudaMemcpyToSymbolAsync(c_b2o, b2o, sizeof(float),        0, cudaMemcpyDeviceToDevice);

    // merged conversion: fp16 table + fp16 layer-1 weights (one kernel)
    unsigned n4 = tot3 / 2;
    convert_kernel<<<(n4 + 255) / 256, 256>>>((const float4*)top, n4, w1o, b1o);

    // fp16 weights scratch -> constant
    void *p_w1h = nullptr, *p_b1h = nullptr;
    cudaGetSymbolAddress(&p_w1h, g_w1h);
    cudaGetSymbolAddress(&p_b1h, g_b1h);
    cudaMemcpyToSymbolAsync(c_w1h, p_w1h, 768 * sizeof(__half2), 0, cudaMemcpyDeviceToDevice);
    cudaMemcpyToSymbolAsync(c_b1h, p_b1h, 32 * sizeof(__half2),  0, cudaMemcpyDeviceToDevice);

    opacity_kernel<<<2 * B, 128>>>(pts, gt, sp3, P, halfP);

    int nb = (B + 127) / 128;
    if (nb > 256) nb = 256;
    conf_kernel<<<nb, 128>>>(line, tconf, sp2, B, 1.0f / (float)P);
    final_kernel<<<1, 256>>>((float*)d_out, nb, 1.0f / (float)B);
}